// round 3
// baseline (speedup 1.0000x reference)
#include <cuda_runtime.h>
#include <stdint.h>

// Problem constants (fixed by the reference)
#define BB 4
#define LL 4096
#define VV 8192
#define NPOS (BB * LL)          // 16384 positions
#define TILE 128
#define NT (VV / TILE)          // 64 tiles per dimension / 64 buckets
#define CAP 2048                // per-bucket capacity (mean 256, sd ~16 -> huge margin)
#define PAD 1

// Scratch (no cudaMalloc allowed)
__device__ int   g_is64;
__device__ int   g_bcount[NT];
__device__ int   g_bpos[NT][CAP];       // packed: (pos << 7) | (idx & 127)
__device__ float g_add[BB][VV];         // 0.01*sigma[b]*rowsum(W)[v] + bias[v]

// ---------------------------------------------------------------------------
// Kernel 1: detect int64-vs-int32 indices, zero bucket counters.
// If indices are int64 (little-endian, values in [0, 8192)), every odd 32-bit
// word of the first 16384 words is a zero high-half. If int32, odd words are
// real random indices (all-zero probability ~ 8192^-8192).
// ---------------------------------------------------------------------------
__global__ void detect_and_zero(const int* __restrict__ idx_words) {
    __shared__ int bad;
    if (threadIdx.x == 0) bad = 0;
    __syncthreads();
    int local = 0;
    for (int i = threadIdx.x; i < NPOS; i += blockDim.x) {
        if ((i & 1) && idx_words[i] != 0) local = 1;
    }
    if (local) atomicOr(&bad, 1);
    __syncthreads();
    if (threadIdx.x == 0) g_is64 = bad ? 0 : 1;
    if (threadIdx.x < NT) g_bcount[threadIdx.x] = 0;
}

// ---------------------------------------------------------------------------
// Kernel 2: counting-sort positions into 64 buckets by idx >> 7.
// ---------------------------------------------------------------------------
__global__ void bucket_build(const void* __restrict__ idxp) {
    int pos = blockIdx.x * blockDim.x + threadIdx.x;
    if (pos >= NPOS) return;
    int is64 = g_is64;
    int idx;
    if (is64) {
        long long raw = ((const long long*)idxp)[pos];
        idx = (int)raw;
    } else {
        idx = ((const int*)idxp)[pos];
    }
    idx = max(0, min(VV - 1, idx));                  // reference clamps
    int bkt = idx >> 7;
    int slot = atomicAdd(&g_bcount[bkt], 1);
    if (slot < CAP)
        g_bpos[bkt][slot] = (pos << 7) | (idx & 127);
}

// ---------------------------------------------------------------------------
// Kernel 3: rowsum(W) + fold sigma/bias -> g_add. One warp per row, float4.
// ---------------------------------------------------------------------------
__global__ void colsum_add(const float* __restrict__ Wm,
                           const float* __restrict__ sigma,
                           const float* __restrict__ bias) {
    int warp = (blockIdx.x * blockDim.x + threadIdx.x) >> 5;
    int lane = threadIdx.x & 31;
    if (warp >= VV) return;
    const float4* row = (const float4*)(Wm + (size_t)warp * VV);
    float s = 0.0f;
#pragma unroll 4
    for (int i = lane; i < VV / 4; i += 32) {
        float4 v = row[i];
        s += (v.x + v.y) + (v.z + v.w);
    }
#pragma unroll
    for (int o = 16; o; o >>= 1) s += __shfl_xor_sync(0xffffffffu, s, o);
    if (lane < BB) {
        g_add[lane][warp] = 0.01f * sigma[lane] * s + bias[warp];
    }
}

// ---------------------------------------------------------------------------
// Kernel 4: tiled transpose-gather. Block = (v-tile, j-bucket).
// Load W[v0:v0+128, j0:j0+128] row-coalesced (float4), transpose into SMEM,
// then stream every position in bucket jb: 128 contiguous output floats each.
// ---------------------------------------------------------------------------
__global__ void gather_kernel(const float* __restrict__ Wm,
                              float* __restrict__ out) {
    extern __shared__ float sm[];            // [TILE][TILE+PAD], sm[j][v]
    const int vt = blockIdx.x;
    const int jb = blockIdx.y;
    const int v0 = vt * TILE;
    const int j0 = jb * TILE;
    const int tid = threadIdx.x;             // 256 threads

    // --- load + transpose tile ---
    const float4* Wp = (const float4*)(Wm + (size_t)v0 * VV + j0);
#pragma unroll 4
    for (int i = tid; i < TILE * (TILE / 4); i += 256) {
        int r  = i >> 5;                      // 0..127 (row within v-tile)
        int c4 = i & 31;                      // float4 index within the 128-col slab
        float4 val = Wp[(size_t)r * (VV / 4) + c4];
        int j = c4 * 4;
        sm[(j + 0) * (TILE + PAD) + r] = val.x;
        sm[(j + 1) * (TILE + PAD) + r] = val.y;
        sm[(j + 2) * (TILE + PAD) + r] = val.z;
        sm[(j + 3) * (TILE + PAD) + r] = val.w;
    }

    // per-thread v lane + preloaded add terms (tiny, L2-hot)
    const int vl = tid & 127;
    const float a0 = g_add[0][v0 + vl];
    const float a1 = g_add[1][v0 + vl];
    const float a2 = g_add[2][v0 + vl];
    const float a3 = g_add[3][v0 + vl];
    __syncthreads();

    // --- epilogue: 2 positions per iteration (tid>>7 selects which) ---
    const int count = min(g_bcount[jb], CAP);
    for (int p = (tid >> 7); p < count; p += 2) {
        int packed = g_bpos[jb][p];
        int pos = packed >> 7;
        int jl  = packed & 127;
        int b   = pos >> 12;                  // LL = 4096
        float add = (b == 0) ? a0 : (b == 1) ? a1 : (b == 2) ? a2 : a3;
        out[(size_t)pos * VV + v0 + vl] = sm[jl * (TILE + PAD) + vl] + add;
    }
}

// ---------------------------------------------------------------------------
// Inputs per metadata order: indices[B,L] (int64 or int32), sigma[B] f32,
// W[V,V] f32, bias[V] f32. Output: float32 [B,L,V].
// ---------------------------------------------------------------------------
extern "C" void kernel_launch(void* const* d_in, const int* in_sizes, int n_in,
                              void* d_out, int out_size) {
    const void*  idx   = d_in[0];
    const float* sigma = (const float*)d_in[1];
    const float* Wm    = (const float*)d_in[2];
    const float* bias  = (const float*)d_in[3];
    float* out = (float*)d_out;

    const int smem = TILE * (TILE + PAD) * (int)sizeof(float);  // 66048 B
    cudaFuncSetAttribute(gather_kernel,
                         cudaFuncAttributeMaxDynamicSharedMemorySize, smem);

    detect_and_zero<<<1, 256>>>((const int*)idx);
    bucket_build<<<NPOS / 256, 256>>>(idx);
    colsum_add<<<(VV * 32) / 256, 256>>>(Wm, sigma, bias);
    gather_kernel<<<dim3(NT, NT), 256, smem>>>(Wm, out);
}

// round 6
// speedup vs baseline: 1.3560x; 1.3560x over previous
#include <cuda_runtime.h>
#include <stdint.h>

// Problem constants (fixed by the reference)
#define BB 4
#define LL 4096
#define VV 8192
#define NPOS (BB * LL)          // 16384 positions
#define TILE 128
#define NT (VV / TILE)          // 64 tiles per dimension / 64 buckets
#define CAP 2048                // per-bucket capacity (mean 256, sd ~16)

// Scratch (no cudaMalloc allowed)
__device__ int   g_is64;
__device__ int   g_bcount[NT];
__device__ int   g_bpos[NT][CAP];       // packed: (pos << 7) | (idx & 127)
__device__ float g_add[BB][VV];         // 0.01*sigma[b]*rowsum(W)[v] + bias[v]

// ---------------------------------------------------------------------------
// Kernel 1: detect int64-vs-int32 indices, zero bucket counters.
// If indices are int64 (LE, values < 8192), every odd 32-bit word is zero.
// ---------------------------------------------------------------------------
__global__ void detect_and_zero(const int* __restrict__ idx_words) {
    __shared__ int bad;
    if (threadIdx.x == 0) bad = 0;
    __syncthreads();
    int local = 0;
    for (int i = threadIdx.x; i < NPOS; i += blockDim.x) {
        if ((i & 1) && idx_words[i] != 0) local = 1;
    }
    if (local) atomicOr(&bad, 1);
    __syncthreads();
    if (threadIdx.x == 0) g_is64 = bad ? 0 : 1;
    if (threadIdx.x < NT) g_bcount[threadIdx.x] = 0;
}

// ---------------------------------------------------------------------------
// Kernel 2: counting-sort positions into 64 buckets by idx >> 7.
// ---------------------------------------------------------------------------
__global__ void bucket_build(const void* __restrict__ idxp) {
    int pos = blockIdx.x * blockDim.x + threadIdx.x;
    if (pos >= NPOS) return;
    int idx;
    if (g_is64) {
        long long raw = ((const long long*)idxp)[pos];
        idx = (int)raw;
    } else {
        idx = ((const int*)idxp)[pos];
    }
    idx = max(0, min(VV - 1, idx));                  // reference clamps
    int bkt = idx >> 7;
    int slot = atomicAdd(&g_bcount[bkt], 1);
    if (slot < CAP)
        g_bpos[bkt][slot] = (pos << 7) | (idx & 127);
}

// ---------------------------------------------------------------------------
// Kernel 3: rowsum(W) + fold sigma/bias -> g_add. One warp per row, float4.
// ---------------------------------------------------------------------------
__global__ void colsum_add(const float* __restrict__ Wm,
                           const float* __restrict__ sigma,
                           const float* __restrict__ bias) {
    int warp = (blockIdx.x * blockDim.x + threadIdx.x) >> 5;
    int lane = threadIdx.x & 31;
    if (warp >= VV) return;
    const float4* row = (const float4*)(Wm + (size_t)warp * VV);
    float s = 0.0f;
#pragma unroll 4
    for (int i = lane; i < VV / 4; i += 32) {
        float4 v = row[i];
        s += (v.x + v.y) + (v.z + v.w);
    }
#pragma unroll
    for (int o = 16; o; o >>= 1) s += __shfl_xor_sync(0xffffffffu, s, o);
    if (lane < BB) {
        g_add[lane][warp] = 0.01f * sigma[lane] * s + bias[warp];
    }
}

// ---------------------------------------------------------------------------
// Kernel 4: tiled transpose-gather, 512 threads, XOR-swizzled smem layout.
//
// Logical transposed element (j, v) lives at float index
//     (j*32 + ((v>>2) ^ (j>>2))) * 4 + (v&3)
// (float4-granularity XOR swizzle). Properties (verified analytically):
//  - load-phase transpose STS: warp covers 4 rows x 8 col-float4s
//    (GMEM: 4 full 128B lines, coalesced); bank = 4*((rgrp^w7)&7) + (r&3)
//    -> 32 distinct banks -> conflict-free.
//  - epilogue LDS.128 for row jl: slot = jl*32 + (lane ^ (jl>>2)), a
//    permutation of 0..31 -> conflict-free.
// Epilogue: one warp per position, one LDS.128 + one STG.128 per lane.
// ---------------------------------------------------------------------------
__global__ void __launch_bounds__(512, 3)
gather_kernel(const float* __restrict__ Wm, float* __restrict__ out) {
    extern __shared__ float smf[];           // 128*128 floats = 64 KB
    const int vt = blockIdx.x;
    const int jb = blockIdx.y;
    const int v0 = vt * TILE;
    const int j0 = jb * TILE;
    const int tid  = threadIdx.x;            // 512 threads
    const int lane = tid & 31;
    const int warp = tid >> 5;               // 0..15

    // --- load + swizzled transpose ---
    const float4* Wp = (const float4*)(Wm + (size_t)v0 * VV + j0);
#pragma unroll
    for (int i = tid; i < TILE * (TILE / 4); i += 512) {
        int seg  = i >> 5;                   // 0..127
        int w    = i & 31;
        int rgrp = seg >> 2;                 // 0..31
        int cgrp = seg & 3;                  // 0..3
        int r    = rgrp * 4 + (w >> 3);      // v-row 0..127
        int c4   = cgrp * 8 + (w & 7);       // float4-col 0..31
        float4 val = Wp[(size_t)r * (VV / 4) + c4];
        int perm = (r >> 2) ^ c4;            // j>>2 == c4 for j in [4c4,4c4+3]
        int vk   = r & 3;
        smf[((4 * c4 + 0) * 32 + perm) * 4 + vk] = val.x;
        smf[((4 * c4 + 1) * 32 + perm) * 4 + vk] = val.y;
        smf[((4 * c4 + 2) * 32 + perm) * 4 + vk] = val.z;
        smf[((4 * c4 + 3) * 32 + perm) * 4 + vk] = val.w;
    }
    __syncthreads();

    // --- epilogue: one warp per position, float4 per lane ---
    const int count = min(g_bcount[jb], CAP);
    const float4* smv = (const float4*)smf;
    const int vlane = v0 + 4 * lane;
    for (int p = warp; p < count; p += 16) {
        int packed = g_bpos[jb][p];           // warp-uniform broadcast load
        int pos = packed >> 7;
        int jl  = packed & 127;
        int b   = pos >> 12;                  // LL = 4096
        float4 add = *(const float4*)&g_add[b][vlane];  // L1-hot
        float4 w4  = smv[jl * 32 + (lane ^ (jl >> 2))]; // conflict-free
        float4 o;
        o.x = w4.x + add.x;
        o.y = w4.y + add.y;
        o.z = w4.z + add.z;
        o.w = w4.w + add.w;
        *(float4*)&out[(size_t)pos * VV + vlane] = o;
    }
}

// ---------------------------------------------------------------------------
// Inputs per metadata order: indices[B,L] (int64 or int32), sigma[B] f32,
// W[V,V] f32, bias[V] f32. Output: float32 [B,L,V].
// ---------------------------------------------------------------------------
extern "C" void kernel_launch(void* const* d_in, const int* in_sizes, int n_in,
                              void* d_out, int out_size) {
    const void*  idx   = d_in[0];
    const float* sigma = (const float*)d_in[1];
    const float* Wm    = (const float*)d_in[2];
    const float* bias  = (const float*)d_in[3];
    float* out = (float*)d_out;

    const int smem = TILE * TILE * (int)sizeof(float);  // 65536 B
    cudaFuncSetAttribute(gather_kernel,
                         cudaFuncAttributeMaxDynamicSharedMemorySize, smem);

    detect_and_zero<<<1, 256>>>((const int*)idx);
    bucket_build<<<NPOS / 256, 256>>>(idx);
    colsum_add<<<(VV * 32) / 256, 256>>>(Wm, sigma, bias);
    gather_kernel<<<dim3(NT, NT), 512, smem>>>(Wm, out);
}